// round 5
// baseline (speedup 1.0000x reference)
#include <cuda_runtime.h>
#include <cuda_fp16.h>
#include <cstdint>

// ---------------- problem constants ----------------
#define BB    32
#define CC    64
#define HW    4096
#define NE    512
#define BCHW  (BB * CC * HW)     // 8388608
#define BHW   (BB * HW)          // 131072
#define MTILE 64                 // tokens per CTA iteration
#define NBLK  (BHW / MTILE)      // 2048
#define NTH   512
#define GRID  148

// ---------------- smem layout (bytes) ----------------
// A (x2 buffers): [k=128 rows][m pad 72 halves] -> row stride 144 B, 18432 B each
// B:   [n=512 rows][k pad 136 halves] -> row stride 272 B, 139264 B
//      (cols 0-63 = e1, cols 64-127 = e2)
#define A_OFF   0
#define A_ROW   144
#define A_BUF   18432
#define B_OFF   (2 * A_BUF)                   // 36864
#define B_ROW   272
#define HN_OFF  (B_OFF + NE * B_ROW)          // 176128
#define PART_OFF (HN_OFF + 2048)              // 178176
#define IND_OFF (PART_OFF + 64 * 9 * 8)       // 182784
#define SMEM_BYTES (IND_OFF + 256)            // 183040

// ---------------- helpers ----------------
__device__ __forceinline__ uint32_t smem_u32(const void* p) {
    uint32_t a;
    asm("{ .reg .u64 t; cvta.to.shared.u64 t, %1; cvt.u32.u64 %0, t; }" : "=r"(a) : "l"(p));
    return a;
}
__device__ __forceinline__ void ldsm_x4(uint32_t* r, uint32_t addr) {
    asm volatile("ldmatrix.sync.aligned.m8n8.x4.shared.b16 {%0,%1,%2,%3}, [%4];"
                 : "=r"(r[0]), "=r"(r[1]), "=r"(r[2]), "=r"(r[3]) : "r"(addr));
}
__device__ __forceinline__ void ldsm_x4_t(uint32_t* r, uint32_t addr) {
    asm volatile("ldmatrix.sync.aligned.m8n8.x4.trans.shared.b16 {%0,%1,%2,%3}, [%4];"
                 : "=r"(r[0]), "=r"(r[1]), "=r"(r[2]), "=r"(r[3]) : "r"(addr));
}
__device__ __forceinline__ void mma16816(float* d, const uint32_t* a, const uint32_t* b) {
    asm volatile("mma.sync.aligned.m16n8k16.row.col.f32.f16.f16.f32 "
                 "{%0,%1,%2,%3}, {%4,%5,%6,%7}, {%8,%9}, {%0,%1,%2,%3};"
                 : "+f"(d[0]), "+f"(d[1]), "+f"(d[2]), "+f"(d[3])
                 : "r"(a[0]), "r"(a[1]), "r"(a[2]), "r"(a[3]), "r"(b[0]), "r"(b[1]));
}
__device__ __forceinline__ uint32_t fmono(float f) {
    uint32_t u = __float_as_uint(f);
    return (u & 0x80000000u) ? ~u : (u | 0x80000000u);
}
__device__ __forceinline__ unsigned long long umax64(unsigned long long a, unsigned long long b) {
    return a > b ? a : b;
}

// ---------------------------------------------------------------------------
// Persistent fused kernel, 16 warps: fp16x3 mma.sync GEMM + argmax + gather.
// Warp (mg, ng): token rows [mg*32, mg*32+32), codes [ng*64, ng*64+64).
// ---------------------------------------------------------------------------
__global__ void __launch_bounds__(NTH, 1)
vq_kernel(const float* __restrict__ x, const float* __restrict__ embed,
          float* __restrict__ o_qwg, float* __restrict__ o_q, float* __restrict__ o_ind)
{
    extern __shared__ char smem[];
    const uint32_t sb = smem_u32(smem);
    const int tid  = threadIdx.x;
    const int lane = tid & 31;
    const int wid  = tid >> 5;           // 0..15
    const int mg   = wid & 1;            // m-group: rows mg*32..mg*32+31
    const int ng   = wid >> 1;           // n-group: codes ng*64..ng*64+63

    // ---- codebook conversion + halfnorms (once per CTA) ----
    {
        int j = tid;                     // code 0..511
        float s = 0.f;
        #pragma unroll 8
        for (int k = 0; k < 64; k++) {
            float val = __ldg(&embed[k * NE + j]);
            half h1 = __float2half_rn(val);
            half h2 = __float2half_rn(val - __half2float(h1));
            *(half*)(smem + B_OFF + j * B_ROW + k * 2)       = h1;
            *(half*)(smem + B_OFF + j * B_ROW + 128 + k * 2) = h2;
            s = fmaf(val, val, s);
        }
        ((float*)(smem + HN_OFF))[j] = 0.5f * s;
    }

    // lane-invariant ldmatrix address parts
    const int lrow = ((lane & 16) >> 1) + (lane & 7);
    const uint32_t a_lane = sb + A_OFF + (uint32_t)lrow * A_ROW + (lane & 8) * 2
                          + (uint32_t)mg * 64;                       // +32 tokens
    const uint32_t b_lane = sb + B_OFF + (uint32_t)(ng * 64 + lrow) * B_ROW + (lane & 8) * 2;

    // k-step schedule: x1*e1, x1*e2, x2*e1
    const int KA[12] = {0,16,32,48,  0,16,32,48, 64,80,96,112};
    const int KB[12] = {0,16,32,48, 64,80,96,112, 0,16,32,48};

    const float* HN = (const float*)(smem + HN_OFF);
    unsigned long long* PART = (unsigned long long*)(smem + PART_OFF);
    int* INDS = (int*)(smem + IND_OFF);
    const int g = lane >> 2, tig = lane & 3;
    const int n0 = ng * 64;
    const int c_ld = tid >> 4, v_ld = tid & 15;   // only meaningful pattern-wise

    // ---- prologue: load + convert + store A[0] for first tile ----
    int tb = blockIdx.x;
    {
        const int b = tb >> 6, t0 = (tb & 63) << 6;
        const float4* xin = (const float4*)(x + (size_t)b * CC * HW) + (t0 >> 2);
        #pragma unroll
        for (int i = 0; i < 2; i++) {
            int idx = tid + i * NTH;
            int c = idx >> 4, v = idx & 15;
            float4 fv = xin[c * (HW / 4) + v];
            float vals[4] = {fv.x, fv.y, fv.z, fv.w};
            #pragma unroll
            for (int p = 0; p < 2; p++) {
                float va = vals[2 * p], vb = vals[2 * p + 1];
                half a1 = __float2half_rn(va), b1 = __float2half_rn(vb);
                half a2 = __float2half_rn(va - __half2float(a1));
                half b2 = __float2half_rn(vb - __half2float(b1));
                int m = 4 * v + 2 * p;
                *(half2*)(smem + c * A_ROW + m * 2)        = __halves2half2(a1, b1);
                *(half2*)(smem + (64 + c) * A_ROW + m * 2) = __halves2half2(a2, b2);
            }
        }
    }
    __syncthreads();

    int it = 0;
    while (tb < NBLK) {
        const int b  = tb >> 6;
        const int t0 = (tb & 63) << 6;
        const int tbn = tb + GRID;
        const bool havenext = tbn < NBLK;
        const uint32_t abuf = a_lane + (uint32_t)((it & 1) * A_BUF);

        // -- prefetch next tile's globals (retire under GEMM) --
        float4 f[2];
        if (havenext) {
            const int bn = tbn >> 6, t0n = (tbn & 63) << 6;
            const float4* xin = (const float4*)(x + (size_t)bn * CC * HW) + (t0n >> 2);
            #pragma unroll
            for (int i = 0; i < 2; i++)
                f[i] = xin[((tid + i * NTH) >> 4) * (HW / 4) + ((tid + i * NTH) & 15)];
        }

        // -- GEMM: warp tile m32 x n64, K=192 via 12 k-steps --
        float acc[2][8][4];
        #pragma unroll
        for (int mt = 0; mt < 2; mt++)
            #pragma unroll
            for (int ni = 0; ni < 8; ni++)
                #pragma unroll
                for (int r = 0; r < 4; r++) acc[mt][ni][r] = 0.f;

        #pragma unroll
        for (int s = 0; s < 12; s++) {
            uint32_t af[2][4], bf[4][4];
            #pragma unroll
            for (int mt = 0; mt < 2; mt++)
                ldsm_x4_t(af[mt], abuf + KA[s] * A_ROW + mt * 32);
            #pragma unroll
            for (int nt = 0; nt < 4; nt++)
                ldsm_x4(bf[nt], b_lane + nt * 16 * B_ROW + KB[s] * 2);
            #pragma unroll
            for (int mt = 0; mt < 2; mt++)
                #pragma unroll
                for (int nt = 0; nt < 4; nt++) {
                    mma16816(acc[mt][nt * 2],     af[mt], &bf[nt][0]);
                    mma16816(acc[mt][nt * 2 + 1], af[mt], &bf[nt][2]);
                }
        }

        // -- fused argmax epilogue --
        {
            float hn[8][2];
            #pragma unroll
            for (int ni = 0; ni < 8; ni++) {
                hn[ni][0] = HN[n0 + ni * 8 + 2 * tig];
                hn[ni][1] = HN[n0 + ni * 8 + 2 * tig + 1];
            }
            #pragma unroll
            for (int mt = 0; mt < 2; mt++) {
                #pragma unroll
                for (int rh = 0; rh < 2; rh++) {
                    unsigned long long best = 0ull;
                    #pragma unroll
                    for (int ni = 0; ni < 8; ni++) {
                        #pragma unroll
                        for (int hc = 0; hc < 2; hc++) {
                            float sc = acc[mt][ni][rh * 2 + hc] - hn[ni][hc];
                            int col = n0 + ni * 8 + 2 * tig + hc;
                            unsigned long long p =
                                ((unsigned long long)fmono(sc) << 32) | (unsigned)(511 - col);
                            best = umax64(best, p);
                        }
                    }
                    best = umax64(best, __shfl_xor_sync(0xffffffffu, best, 1));
                    best = umax64(best, __shfl_xor_sync(0xffffffffu, best, 2));
                    if (tig == 0) {
                        int tok = mg * 32 + mt * 16 + rh * 8 + g;
                        PART[tok * 9 + ng] = best;
                    }
                }
            }
        }
        __syncthreads();

        if (tid < 64) {
            unsigned long long m = PART[tid * 9];
            #pragma unroll
            for (int ww = 1; ww < 8; ww++) m = umax64(m, PART[tid * 9 + ww]);
            int code = 511 - (int)(unsigned)(m & 0xffffffffu);
            INDS[tid] = code;
            if (o_ind) o_ind[(size_t)b * HW + t0 + tid] = (float)code;
        }
        __syncthreads();

        // -- fused gather + NCHW writes (fire-and-forget STGs) --
        {
            #pragma unroll
            for (int i = 0; i < 2; i++) {
                int idx = tid + i * NTH;
                int c = idx >> 4, v = idx & 15;
                float4 o;
                float* op = &o.x;
                #pragma unroll
                for (int e = 0; e < 4; e++) {
                    int code = INDS[4 * v + e];
                    float v1 = __half2float(*(const half*)(smem + B_OFF + code * B_ROW + c * 2));
                    float v2 = __half2float(*(const half*)(smem + B_OFF + code * B_ROW + 128 + c * 2));
                    op[e] = v1 + v2;
                }
                size_t off = (size_t)b * CC * HW + (size_t)c * HW + t0 + 4 * v;
                *(float4*)(o_qwg + off) = o;
                if (o_q) *(float4*)(o_q + off) = o;
            }
        }

        // -- convert + store next A tile into the other buffer --
        if (havenext) {
            char* adst = smem + ((it + 1) & 1) * A_BUF;
            #pragma unroll
            for (int i = 0; i < 2; i++) {
                int idx = tid + i * NTH;
                int c = idx >> 4, v = idx & 15;
                float vals[4] = {f[i].x, f[i].y, f[i].z, f[i].w};
                #pragma unroll
                for (int p = 0; p < 2; p++) {
                    float va = vals[2 * p], vb = vals[2 * p + 1];
                    half a1 = __float2half_rn(va), b1 = __float2half_rn(vb);
                    half a2 = __float2half_rn(va - __half2float(a1));
                    half b2 = __float2half_rn(vb - __half2float(b1));
                    int m = 4 * v + 2 * p;
                    *(half2*)(adst + c * A_ROW + m * 2)        = __halves2half2(a1, b1);
                    *(half2*)(adst + (64 + c) * A_ROW + m * 2) = __halves2half2(a2, b2);
                }
            }
        }
        __syncthreads();

        tb = tbn;
        it++;
    }
}

// ---------------------------------------------------------------------------
extern "C" void kernel_launch(void* const* d_in, const int* in_sizes, int n_in,
                              void* d_out, int out_size)
{
    const float* x     = (const float*)d_in[0];
    const float* embed = (const float*)d_in[1];
    float* out = (float*)d_out;

    float* o_qwg = out;
    float* o_q   = nullptr;
    float* o_ind = nullptr;
    long os = out_size;
    if (os >= 2L * BCHW + BHW)       { o_q = out + BCHW; o_ind = out + 2L * BCHW; }
    else if (os >= 2L * BCHW)        { o_q = out + BCHW; }
    else if (os >= (long)BCHW + BHW) { o_ind = out + BCHW; }

    cudaFuncSetAttribute(vq_kernel,
                         cudaFuncAttributeMaxDynamicSharedMemorySize, SMEM_BYTES);

    vq_kernel<<<GRID, NTH, SMEM_BYTES>>>(x, embed, o_qwg, o_q, o_ind);
}

// round 7
// speedup vs baseline: 1.2643x; 1.2643x over previous
#include <cuda_runtime.h>
#include <cuda_fp16.h>
#include <cstdint>

// ---------------- problem constants ----------------
#define BB    32
#define CC    64
#define HW    4096
#define NE    512
#define BCHW  (BB * CC * HW)     // 8388608
#define BHW   (BB * HW)          // 131072
#define MTILE 64
#define NBLK  (BHW / MTILE)      // 2048
#define NTH   256
#define STREAMS 148
#define GRID  (STREAMS * 2)

// ---------------- smem layout (bytes) ----------------
// A: [k=128 rows][m pad 72 halves] -> 144 B/row, 18432 B
// B: [n=256 rows][k pad 136 halves] -> 272 B/row, 69632 B (e1 k0-63 | e2 k64-127)
#define A_OFF   0
#define A_ROW   144
#define B_OFF   18432
#define B_ROW   272
#define HN_OFF  (B_OFF + 256 * B_ROW)         // 88064
#define PART_OFF (HN_OFF + 1024)              // 89088
#define SMEM_BYTES (PART_OFF + 64 * 9 * 8)    // 93696

// ---------------- scratch ----------------
__device__ unsigned long long g_part[2][BHW];
__device__ int g_ind[BHW];

// ---------------- helpers ----------------
__device__ __forceinline__ uint32_t smem_u32(const void* p) {
    uint32_t a;
    asm("{ .reg .u64 t; cvta.to.shared.u64 t, %1; cvt.u32.u64 %0, t; }" : "=r"(a) : "l"(p));
    return a;
}
__device__ __forceinline__ void ldsm_x4(uint32_t* r, uint32_t addr) {
    asm volatile("ldmatrix.sync.aligned.m8n8.x4.shared.b16 {%0,%1,%2,%3}, [%4];"
                 : "=r"(r[0]), "=r"(r[1]), "=r"(r[2]), "=r"(r[3]) : "r"(addr));
}
__device__ __forceinline__ void ldsm_x4_t(uint32_t* r, uint32_t addr) {
    asm volatile("ldmatrix.sync.aligned.m8n8.x4.trans.shared.b16 {%0,%1,%2,%3}, [%4];"
                 : "=r"(r[0]), "=r"(r[1]), "=r"(r[2]), "=r"(r[3]) : "r"(addr));
}
__device__ __forceinline__ void mma16816(float* d, const uint32_t* a, const uint32_t* b) {
    asm volatile("mma.sync.aligned.m16n8k16.row.col.f32.f16.f16.f32 "
                 "{%0,%1,%2,%3}, {%4,%5,%6,%7}, {%8,%9}, {%0,%1,%2,%3};"
                 : "+f"(d[0]), "+f"(d[1]), "+f"(d[2]), "+f"(d[3])
                 : "r"(a[0]), "r"(a[1]), "r"(a[2]), "r"(a[3]), "r"(b[0]), "r"(b[1]));
}
__device__ __forceinline__ uint32_t fmono(float f) {
    uint32_t u = __float_as_uint(f);
    return (u & 0x80000000u) ? ~u : (u | 0x80000000u);
}
__device__ __forceinline__ unsigned long long umax64(unsigned long long a, unsigned long long b) {
    return a > b ? a : b;
}

// ---------------------------------------------------------------------------
// Kernel 1: half-codebook fp16x3 mma.sync GEMM + fused argmax -> u64 partials.
// grid 296 = 148 streams x 2 codebook halves; 2 CTAs co-resident per SM.
// Warp w (0..7) owns local codes [w*32, w*32+32), full m64.
// ---------------------------------------------------------------------------
__global__ void __launch_bounds__(NTH, 2)
vq_mma_kernel(const float* __restrict__ x, const float* __restrict__ embed)
{
    extern __shared__ char smem[];
    const uint32_t sb = smem_u32(smem);
    const int tid  = threadIdx.x;
    const int lane = tid & 31;
    const int w    = tid >> 5;
    const int hf     = blockIdx.x & 1;       // codebook half (NOT named 'half'!)
    const int stream = blockIdx.x >> 1;
    const int c0     = hf * 256;

    // ---- half-codebook conversion + halfnorms (once) ----
    {
        int jl = tid;                    // local code 0..255
        float s = 0.f;
        #pragma unroll 8
        for (int k = 0; k < 64; k++) {
            float val = __ldg(&embed[k * NE + c0 + jl]);
            half h1 = __float2half_rn(val);
            half h2 = __float2half_rn(val - __half2float(h1));
            *(half*)(smem + B_OFF + jl * B_ROW + k * 2)       = h1;
            *(half*)(smem + B_OFF + jl * B_ROW + 128 + k * 2) = h2;
            s = fmaf(val, val, s);
        }
        ((float*)(smem + HN_OFF))[jl] = 0.5f * s;
    }

    // lane-invariant ldmatrix address parts
    const int lrow = ((lane & 16) >> 1) + (lane & 7);
    const uint32_t a_lane = sb + A_OFF + (uint32_t)lrow * A_ROW + (lane & 8) * 2;
    const uint32_t b_lane = sb + B_OFF + (uint32_t)(w * 32 + lrow) * B_ROW + (lane & 8) * 2;

    // k-step schedule: x1*e1, x1*e2, x2*e1
    const int KA[12] = {0,16,32,48,  0,16,32,48, 64,80,96,112};
    const int KB[12] = {0,16,32,48, 64,80,96,112, 0,16,32,48};

    const float* HN = (const float*)(smem + HN_OFF);
    unsigned long long* PART = (unsigned long long*)(smem + PART_OFF);
    const int g = lane >> 2, tig = lane & 3;

    // per-thread halfnorms for owned columns
    float hn[4][2];
    #pragma unroll
    for (int nn = 0; nn < 4; nn++) {
        hn[nn][0] = HN[w * 32 + nn * 8 + 2 * tig];
        hn[nn][1] = HN[w * 32 + nn * 8 + 2 * tig + 1];
    }

    int tb = stream;
    // prologue load
    float4 f[4];
    {
        const int b = tb >> 6, t0 = (tb & 63) << 6;
        const float4* xin = (const float4*)(x + (size_t)b * CC * HW) + (t0 >> 2);
        #pragma unroll
        for (int i = 0; i < 4; i++)
            f[i] = xin[((tid + i * NTH) >> 4) * (HW / 4) + ((tid + i * NTH) & 15)];
    }

    while (tb < NBLK) {
        // -- convert + store A tile (safe: prior GEMM reads done at last sync) --
        #pragma unroll
        for (int i = 0; i < 4; i++) {
            int idx = tid + i * NTH;
            int c = idx >> 4, v = idx & 15;
            float vals[4] = {f[i].x, f[i].y, f[i].z, f[i].w};
            #pragma unroll
            for (int p = 0; p < 2; p++) {
                float va = vals[2 * p], vb = vals[2 * p + 1];
                half a1 = __float2half_rn(va);
                half b1 = __float2half_rn(vb);
                half a2 = __float2half_rn(va - __half2float(a1));
                half b2 = __float2half_rn(vb - __half2float(b1));
                int m = 4 * v + 2 * p;
                *(half2*)(smem + A_OFF + c * A_ROW + m * 2)        = __halves2half2(a1, b1);
                *(half2*)(smem + A_OFF + (64 + c) * A_ROW + m * 2) = __halves2half2(a2, b2);
            }
        }
        __syncthreads();

        const int tbn = tb + STREAMS;
        if (tbn < NBLK) {
            const int bn = tbn >> 6, t0n = (tbn & 63) << 6;
            const float4* xin = (const float4*)(x + (size_t)bn * CC * HW) + (t0n >> 2);
            #pragma unroll
            for (int i = 0; i < 4; i++)
                f[i] = xin[((tid + i * NTH) >> 4) * (HW / 4) + ((tid + i * NTH) & 15)];
        }

        // -- GEMM: warp tile m64 x n32, K=192 via 12 k-steps --
        float acc[4][4][4];
        #pragma unroll
        for (int mt = 0; mt < 4; mt++)
            #pragma unroll
            for (int nn = 0; nn < 4; nn++)
                #pragma unroll
                for (int r = 0; r < 4; r++) acc[mt][nn][r] = 0.f;

        #pragma unroll
        for (int s = 0; s < 12; s++) {
            uint32_t af[4][4], bf[2][4];
            #pragma unroll
            for (int mt = 0; mt < 4; mt++)
                ldsm_x4_t(af[mt], a_lane + KA[s] * A_ROW + mt * 32);
            #pragma unroll
            for (int nt = 0; nt < 2; nt++)
                ldsm_x4(bf[nt], b_lane + nt * 16 * B_ROW + KB[s] * 2);
            #pragma unroll
            for (int mt = 0; mt < 4; mt++)
                #pragma unroll
                for (int nt = 0; nt < 2; nt++) {
                    mma16816(acc[mt][nt * 2],     af[mt], &bf[nt][0]);
                    mma16816(acc[mt][nt * 2 + 1], af[mt], &bf[nt][2]);
                }
        }

        // -- fused argmax over this warp's 32 codes --
        #pragma unroll
        for (int mt = 0; mt < 4; mt++) {
            #pragma unroll
            for (int rh = 0; rh < 2; rh++) {
                unsigned long long best = 0ull;
                #pragma unroll
                for (int nn = 0; nn < 4; nn++) {
                    #pragma unroll
                    for (int hc = 0; hc < 2; hc++) {
                        float sc = acc[mt][nn][rh * 2 + hc] - hn[nn][hc];
                        int code = c0 + w * 32 + nn * 8 + 2 * tig + hc;
                        unsigned long long p =
                            ((unsigned long long)fmono(sc) << 32) | (unsigned)(511 - code);
                        best = umax64(best, p);
                    }
                }
                best = umax64(best, __shfl_xor_sync(0xffffffffu, best, 1));
                best = umax64(best, __shfl_xor_sync(0xffffffffu, best, 2));
                if (tig == 0)
                    PART[(mt * 16 + rh * 8 + g) * 9 + w] = best;
            }
        }
        __syncthreads();

        if (tid < 64) {
            unsigned long long m = PART[tid * 9];
            #pragma unroll
            for (int ww = 1; ww < 8; ww++) m = umax64(m, PART[tid * 9 + ww]);
            g_part[hf][tb * MTILE + tid] = m;   // token = tb*64 + tid
        }
        tb = tbn;
    }
}

// ---------------------------------------------------------------------------
// Kernel 2: merge halves (packed 511-code keeps lowest-index tie-break).
// ---------------------------------------------------------------------------
__global__ void vq_resolve_kernel(float* __restrict__ o_ind)
{
    int n = blockIdx.x * blockDim.x + threadIdx.x;
    if (n < BHW) {
        unsigned long long m = umax64(g_part[0][n], g_part[1][n]);
        int code = 511 - (int)(unsigned)(m & 0xffffffffu);
        g_ind[n] = code;
        if (o_ind) o_ind[n] = (float)code;
    }
}

// ---------------------------------------------------------------------------
// Kernel 3: gather codebook -> NCHW, float4 loads/stores, both outputs.
// ---------------------------------------------------------------------------
__global__ void vq_gather_kernel(const float* __restrict__ embed,
                                 float* __restrict__ o_qwg,
                                 float* __restrict__ o_q)
{
    int i = blockIdx.x * blockDim.x + threadIdx.x;   // over BCHW/4
    if (i >= BCHW / 4) return;
    int t4 = i & (HW / 4 - 1);
    int c  = (i >> 10) & (CC - 1);
    int b  = i >> 16;
    int4 id4 = *(const int4*)(g_ind + b * HW + 4 * t4);
    const float* er = embed + c * NE;
    float4 v;
    v.x = __ldg(er + id4.x); v.y = __ldg(er + id4.y);
    v.z = __ldg(er + id4.z); v.w = __ldg(er + id4.w);
    ((float4*)o_qwg)[i] = v;
    if (o_q) ((float4*)o_q)[i] = v;
}

// ---------------------------------------------------------------------------
extern "C" void kernel_launch(void* const* d_in, const int* in_sizes, int n_in,
                              void* d_out, int out_size)
{
    const float* x     = (const float*)d_in[0];
    const float* embed = (const float*)d_in[1];
    float* out = (float*)d_out;

    float* o_qwg = out;
    float* o_q   = nullptr;
    float* o_ind = nullptr;
    long os = out_size;
    if (os >= 2L * BCHW + BHW)       { o_q = out + BCHW; o_ind = out + 2L * BCHW; }
    else if (os >= 2L * BCHW)        { o_q = out + BCHW; }
    else if (os >= (long)BCHW + BHW) { o_ind = out + BCHW; }

    cudaFuncSetAttribute(vq_mma_kernel,
                         cudaFuncAttributeMaxDynamicSharedMemorySize, SMEM_BYTES);

    vq_mma_kernel<<<GRID, NTH, SMEM_BYTES>>>(x, embed);
    vq_resolve_kernel<<<(BHW + 255) / 256, 256>>>(o_ind);
    vq_gather_kernel<<<(BCHW / 4 + 255) / 256, 256>>>(embed, o_qwg, o_q);
}

// round 8
// speedup vs baseline: 1.2693x; 1.0039x over previous
#include <cuda_runtime.h>
#include <cuda_fp16.h>
#include <cstdint>

// ---------------- problem constants ----------------
#define BB    32
#define CC    64
#define HW    4096
#define NE    512
#define BCHW  (BB * CC * HW)     // 8388608
#define BHW   (BB * HW)          // 131072
#define MTILE 64
#define NBLK  (BHW / MTILE)      // 2048
#define NTH   256
#define STREAMS 148
#define GRID  (STREAMS * 2)

// ---------------- smem layout (bytes) ----------------
// A: [k=128 rows][m pad 72 halves] -> 144 B/row, 18432 B
// B: [n=256 rows][k pad 136 halves] -> 272 B/row, 69632 B (e1 k0-63 | e2 k64-127)
#define A_OFF   0
#define A_ROW   144
#define B_OFF   18432
#define B_ROW   272
#define HN_OFF  (B_OFF + 256 * B_ROW)         // 88064
#define PART_OFF (HN_OFF + 1024)              // 89088
#define SMEM_BYTES (PART_OFF + 64 * 9 * 8)    // 93696

// ---------------- scratch ----------------
__device__ unsigned long long g_part[2][BHW];
__device__ int g_ind[BHW];

// ---------------- helpers ----------------
__device__ __forceinline__ uint32_t smem_u32(const void* p) {
    uint32_t a;
    asm("{ .reg .u64 t; cvta.to.shared.u64 t, %1; cvt.u32.u64 %0, t; }" : "=r"(a) : "l"(p));
    return a;
}
__device__ __forceinline__ void ldsm_x4(uint32_t* r, uint32_t addr) {
    asm volatile("ldmatrix.sync.aligned.m8n8.x4.shared.b16 {%0,%1,%2,%3}, [%4];"
                 : "=r"(r[0]), "=r"(r[1]), "=r"(r[2]), "=r"(r[3]) : "r"(addr));
}
__device__ __forceinline__ void ldsm_x4_t(uint32_t* r, uint32_t addr) {
    asm volatile("ldmatrix.sync.aligned.m8n8.x4.trans.shared.b16 {%0,%1,%2,%3}, [%4];"
                 : "=r"(r[0]), "=r"(r[1]), "=r"(r[2]), "=r"(r[3]) : "r"(addr));
}
__device__ __forceinline__ void mma16816(float* d, const uint32_t* a, const uint32_t* b) {
    asm volatile("mma.sync.aligned.m16n8k16.row.col.f32.f16.f16.f32 "
                 "{%0,%1,%2,%3}, {%4,%5,%6,%7}, {%8,%9}, {%0,%1,%2,%3};"
                 : "+f"(d[0]), "+f"(d[1]), "+f"(d[2]), "+f"(d[3])
                 : "r"(a[0]), "r"(a[1]), "r"(a[2]), "r"(a[3]), "r"(b[0]), "r"(b[1]));
}
__device__ __forceinline__ uint32_t fmono(float f) {
    uint32_t u = __float_as_uint(f);
    return (u & 0x80000000u) ? ~u : (u | 0x80000000u);
}
__device__ __forceinline__ unsigned long long umax64(unsigned long long a, unsigned long long b) {
    return a > b ? a : b;
}

// ---------------------------------------------------------------------------
// Kernel 1: half-codebook fp16x3 mma.sync GEMM + fused argmax -> u64 partials.
// grid 296 = 148 streams x 2 codebook halves; 2 CTAs co-resident per SM.
// Warp w (0..7) owns local codes [w*32, w*32+32), full m64.
// ---------------------------------------------------------------------------
__global__ void __launch_bounds__(NTH, 2)
vq_mma_kernel(const float* __restrict__ x, const float* __restrict__ embed)
{
    extern __shared__ char smem[];
    const uint32_t sb = smem_u32(smem);
    const int tid  = threadIdx.x;
    const int lane = tid & 31;
    const int w    = tid >> 5;
    const int hf     = blockIdx.x & 1;       // codebook half (NOT named 'half'!)
    const int stream = blockIdx.x >> 1;
    const int c0     = hf * 256;

    // ---- half-codebook conversion + halfnorms (once) ----
    {
        int jl = tid;                    // local code 0..255
        float s = 0.f;
        #pragma unroll 8
        for (int k = 0; k < 64; k++) {
            float val = __ldg(&embed[k * NE + c0 + jl]);
            half h1 = __float2half_rn(val);
            half h2 = __float2half_rn(val - __half2float(h1));
            *(half*)(smem + B_OFF + jl * B_ROW + k * 2)       = h1;
            *(half*)(smem + B_OFF + jl * B_ROW + 128 + k * 2) = h2;
            s = fmaf(val, val, s);
        }
        ((float*)(smem + HN_OFF))[jl] = 0.5f * s;
    }

    // lane-invariant ldmatrix address parts
    const int lrow = ((lane & 16) >> 1) + (lane & 7);
    const uint32_t a_lane = sb + A_OFF + (uint32_t)lrow * A_ROW + (lane & 8) * 2;
    const uint32_t b_lane = sb + B_OFF + (uint32_t)(w * 32 + lrow) * B_ROW + (lane & 8) * 2;

    // k-step schedule: x1*e1, x1*e2, x2*e1
    const int KA[12] = {0,16,32,48,  0,16,32,48, 64,80,96,112};
    const int KB[12] = {0,16,32,48, 64,80,96,112, 0,16,32,48};

    const float* HN = (const float*)(smem + HN_OFF);
    unsigned long long* PART = (unsigned long long*)(smem + PART_OFF);
    const int g = lane >> 2, tig = lane & 3;

    // per-thread halfnorms for owned columns
    float hn[4][2];
    #pragma unroll
    for (int nn = 0; nn < 4; nn++) {
        hn[nn][0] = HN[w * 32 + nn * 8 + 2 * tig];
        hn[nn][1] = HN[w * 32 + nn * 8 + 2 * tig + 1];
    }

    int tb = stream;
    // prologue load
    float4 f[4];
    {
        const int b = tb >> 6, t0 = (tb & 63) << 6;
        const float4* xin = (const float4*)(x + (size_t)b * CC * HW) + (t0 >> 2);
        #pragma unroll
        for (int i = 0; i < 4; i++)
            f[i] = xin[((tid + i * NTH) >> 4) * (HW / 4) + ((tid + i * NTH) & 15)];
    }

    while (tb < NBLK) {
        // -- convert + store A tile (safe: prior GEMM reads done at last sync) --
        #pragma unroll
        for (int i = 0; i < 4; i++) {
            int idx = tid + i * NTH;
            int c = idx >> 4, v = idx & 15;
            float vals[4] = {f[i].x, f[i].y, f[i].z, f[i].w};
            #pragma unroll
            for (int p = 0; p < 2; p++) {
                float va = vals[2 * p], vb = vals[2 * p + 1];
                half a1 = __float2half_rn(va);
                half b1 = __float2half_rn(vb);
                half a2 = __float2half_rn(va - __half2float(a1));
                half b2 = __float2half_rn(vb - __half2float(b1));
                int m = 4 * v + 2 * p;
                *(half2*)(smem + A_OFF + c * A_ROW + m * 2)        = __halves2half2(a1, b1);
                *(half2*)(smem + A_OFF + (64 + c) * A_ROW + m * 2) = __halves2half2(a2, b2);
            }
        }
        __syncthreads();

        const int tbn = tb + STREAMS;
        if (tbn < NBLK) {
            const int bn = tbn >> 6, t0n = (tbn & 63) << 6;
            const float4* xin = (const float4*)(x + (size_t)bn * CC * HW) + (t0n >> 2);
            #pragma unroll
            for (int i = 0; i < 4; i++)
                f[i] = xin[((tid + i * NTH) >> 4) * (HW / 4) + ((tid + i * NTH) & 15)];
        }

        // -- GEMM: warp tile m64 x n32, K=192 via 12 k-steps --
        float acc[4][4][4];
        #pragma unroll
        for (int mt = 0; mt < 4; mt++)
            #pragma unroll
            for (int nn = 0; nn < 4; nn++)
                #pragma unroll
                for (int r = 0; r < 4; r++) acc[mt][nn][r] = 0.f;

        #pragma unroll
        for (int s = 0; s < 12; s++) {
            uint32_t af[4][4], bf[2][4];
            #pragma unroll
            for (int mt = 0; mt < 4; mt++)
                ldsm_x4_t(af[mt], a_lane + KA[s] * A_ROW + mt * 32);
            #pragma unroll
            for (int nt = 0; nt < 2; nt++)
                ldsm_x4(bf[nt], b_lane + nt * 16 * B_ROW + KB[s] * 2);
            #pragma unroll
            for (int mt = 0; mt < 4; mt++)
                #pragma unroll
                for (int nt = 0; nt < 2; nt++) {
                    mma16816(acc[mt][nt * 2],     af[mt], &bf[nt][0]);
                    mma16816(acc[mt][nt * 2 + 1], af[mt], &bf[nt][2]);
                }
        }

        // -- fused argmax over this warp's 32 codes --
        #pragma unroll
        for (int mt = 0; mt < 4; mt++) {
            #pragma unroll
            for (int rh = 0; rh < 2; rh++) {
                unsigned long long best = 0ull;
                #pragma unroll
                for (int nn = 0; nn < 4; nn++) {
                    #pragma unroll
                    for (int hc = 0; hc < 2; hc++) {
                        float sc = acc[mt][nn][rh * 2 + hc] - hn[nn][hc];
                        int code = c0 + w * 32 + nn * 8 + 2 * tig + hc;
                        unsigned long long p =
                            ((unsigned long long)fmono(sc) << 32) | (unsigned)(511 - code);
                        best = umax64(best, p);
                    }
                }
                best = umax64(best, __shfl_xor_sync(0xffffffffu, best, 1));
                best = umax64(best, __shfl_xor_sync(0xffffffffu, best, 2));
                if (tig == 0)
                    PART[(mt * 16 + rh * 8 + g) * 9 + w] = best;
            }
        }
        __syncthreads();

        if (tid < 64) {
            unsigned long long m = PART[tid * 9];
            #pragma unroll
            for (int ww = 1; ww < 8; ww++) m = umax64(m, PART[tid * 9 + ww]);
            g_part[hf][tb * MTILE + tid] = m;   // token = tb*64 + tid
        }
        tb = tbn;
    }
}

// ---------------------------------------------------------------------------
// Kernel 2: merge halves (packed 511-code keeps lowest-index tie-break).
// ---------------------------------------------------------------------------
__global__ void vq_resolve_kernel(float* __restrict__ o_ind)
{
    int n = blockIdx.x * blockDim.x + threadIdx.x;
    if (n < BHW) {
        unsigned long long m = umax64(g_part[0][n], g_part[1][n]);
        int code = 511 - (int)(unsigned)(m & 0xffffffffu);
        g_ind[n] = code;
        if (o_ind) o_ind[n] = (float)code;
    }
}

// ---------------------------------------------------------------------------
// Kernel 3: gather codebook -> NCHW, float4 loads/stores, both outputs.
// ---------------------------------------------------------------------------
__global__ void vq_gather_kernel(const float* __restrict__ embed,
                                 float* __restrict__ o_qwg,
                                 float* __restrict__ o_q)
{
    int i = blockIdx.x * blockDim.x + threadIdx.x;   // over BCHW/4
    if (i >= BCHW / 4) return;
    int t4 = i & (HW / 4 - 1);
    int c  = (i >> 10) & (CC - 1);
    int b  = i >> 16;
    int4 id4 = *(const int4*)(g_ind + b * HW + 4 * t4);
    const float* er = embed + c * NE;
    float4 v;
    v.x = __ldg(er + id4.x); v.y = __ldg(er + id4.y);
    v.z = __ldg(er + id4.z); v.w = __ldg(er + id4.w);
    ((float4*)o_qwg)[i] = v;
    if (o_q) ((float4*)o_q)[i] = v;
}

// ---------------------------------------------------------------------------
extern "C" void kernel_launch(void* const* d_in, const int* in_sizes, int n_in,
                              void* d_out, int out_size)
{
    const float* x     = (const float*)d_in[0];
    const float* embed = (const float*)d_in[1];
    float* out = (float*)d_out;

    float* o_qwg = out;
    float* o_q   = nullptr;
    float* o_ind = nullptr;
    long os = out_size;
    if (os >= 2L * BCHW + BHW)       { o_q = out + BCHW; o_ind = out + 2L * BCHW; }
    else if (os >= 2L * BCHW)        { o_q = out + BCHW; }
    else if (os >= (long)BCHW + BHW) { o_ind = out + BCHW; }

    cudaFuncSetAttribute(vq_mma_kernel,
                         cudaFuncAttributeMaxDynamicSharedMemorySize, SMEM_BYTES);

    vq_mma_kernel<<<GRID, NTH, SMEM_BYTES>>>(x, embed);
    vq_resolve_kernel<<<(BHW + 255) / 256, 256>>>(o_ind);
    vq_gather_kernel<<<(BCHW / 4 + 255) / 256, 256>>>(embed, o_qwg, o_q);
}